// round 8
// baseline (speedup 1.0000x reference)
#include <cuda_runtime.h>
#include <math.h>
#include <float.h>

#define NPTS 8192
#define BATCH 2
#define VOXD 64
#define VOXH 128
#define VOXW 128
#define VOX (VOXD*VOXH*VOXW)
#define DPIX (512*512)

// block layout: 512 threads each. aux first (cheap), chamfer 48..175.
#define CL_BLKS   32
#define DP_BLKS   16
#define AUX_BLKS  (CL_BLKS + DP_BLKS)          // 48
#define CHAM_BLKS 128
#define TOT_BLKS  (AUX_BLKS + CHAM_BLKS)       // 176

// partials
__device__ float g_cham[CHAM_BLKS];       // per-block sum of min dists
__device__ float g_cl[BATCH * 16 * 3];    // inter, psum, gsum   (16 blocks/batch)
__device__ float g_dp[BATCH * 8 * 6];     // g, g2, gx, gy, l1, mask (8 blocks/batch)
__device__ unsigned int g_cnt = 0;        // completion counter (self-resetting)

// ---------------- helpers ----------------
__device__ __forceinline__ unsigned long long pack2(float a, float b) {
    unsigned long long r;
    asm("mov.b64 %0, {%1, %2};" : "=l"(r) : "f"(a), "f"(b));
    return r;
}
__device__ __forceinline__ unsigned long long fma2(unsigned long long a,
                                                   unsigned long long b,
                                                   unsigned long long c) {
    unsigned long long d;
    asm("fma.rn.f32x2 %0, %1, %2, %3;" : "=l"(d) : "l"(a), "l"(b), "l"(c));
    return d;
}
__device__ __forceinline__ float lo2(unsigned long long v) {
    return __uint_as_float((unsigned)v);
}
__device__ __forceinline__ float hi2(unsigned long long v) {
    return __uint_as_float((unsigned)(v >> 32));
}
__device__ __forceinline__ float warp_sum(float v) {
#pragma unroll
    for (int o = 16; o > 0; o >>= 1) v += __shfl_xor_sync(0xffffffffu, v, o);
    return v;
}
__device__ __forceinline__ float min3f(float a, float b, float c) {
    return fminf(a, fminf(b, c));
}

// ===========================================================================
// Mega kernel with in-kernel finalize (last-block pattern).
// ===========================================================================
__global__ void __launch_bounds__(512, 2) mega_kernel(const float* __restrict__ pc,
                                                      const float* __restrict__ pv,
                                                      const float* __restrict__ pd,
                                                      const float* __restrict__ gp,
                                                      const float* __restrict__ gv,
                                                      const float* __restrict__ gd,
                                                      const float* __restrict__ dm,
                                                      const int* __restrict__ iter,
                                                      float* __restrict__ out) {
    // chamfer tiles: 4 q-quarter groups, each 256 q packed as f32x2 pairs
    __shared__ __align__(16) float smA[4][512];   // (qx0,qx1,qy0,qy1) per pair
    __shared__ __align__(16) float smB[4][512];   // (qz0,qz1,s0,s1) per pair
    __shared__ float smC[512][2];                 // per-thread quarter mins
    __shared__ float sred[18];
    __shared__ unsigned int sflag;

    const int bid = blockIdx.x;
    const int tid = threadIdx.x;
    const int lane = tid & 31;
    const int wid = tid >> 5;

    if (bid >= AUX_BLKS) {
        // ---------------- chamfer (128 blocks, 256 A pts each) ----------------
        // d = |p|^2 + |q|^2 - 2 p.q = p2 + 2*(s - p.q), s = |q|^2/2
        const int cr = bid - AUX_BLKS;
        const int dir = cr >> 6;
        const int b = (cr >> 5) & 1;
        const int chunk = cr & 31;
        const float* A  = (dir == 0 ? pc : gp) + (size_t)b * NPTS * 3;
        const float* Bp = (dir == 0 ? gp : pc) + (size_t)b * NPTS * 3;

        const int ap = tid & 127;     // A-pair index within block
        const int qq = tid >> 7;      // q quarter 0..3

        const int i0 = chunk * 256 + ap * 2;
        const float ax0 = A[i0 * 3 + 0], ay0 = A[i0 * 3 + 1], az0 = A[i0 * 3 + 2];
        const float ax1 = A[i0 * 3 + 3], ay1 = A[i0 * 3 + 4], az1 = A[i0 * 3 + 5];
        const float p2_0 = fmaf(ax0, ax0, fmaf(ay0, ay0, az0 * az0));
        const float p2_1 = fmaf(ax1, ax1, fmaf(ay1, ay1, az1 * az1));

        const unsigned long long nx0 = pack2(-ax0, -ax0);
        const unsigned long long ny0 = pack2(-ay0, -ay0);
        const unsigned long long nz0 = pack2(-az0, -az0);
        const unsigned long long nx1 = pack2(-ax1, -ax1);
        const unsigned long long ny1 = pack2(-ay1, -ay1);
        const unsigned long long nz1 = pack2(-az1, -az1);

        float bl0 = FLT_MAX, bh0 = FLT_MAX, bl1 = FLT_MAX, bh1 = FLT_MAX;

        const int qbase = qq * 2048;
#pragma unroll 1
        for (int t0 = 0; t0 < 2048; t0 += 256) {
            // group qq loads its own 256-q tile (2 q per thread)
            const int j = qbase + t0 + ap * 2;
            const float qx0 = Bp[j * 3 + 0], qy0 = Bp[j * 3 + 1], qz0 = Bp[j * 3 + 2];
            const float qx1 = Bp[j * 3 + 3], qy1 = Bp[j * 3 + 4], qz1 = Bp[j * 3 + 5];
            const float s0 = 0.5f * fmaf(qx0, qx0, fmaf(qy0, qy0, qz0 * qz0));
            const float s1 = 0.5f * fmaf(qx1, qx1, fmaf(qy1, qy1, qz1 * qz1));
            __syncthreads();
            smA[qq][ap * 4 + 0] = qx0;
            smA[qq][ap * 4 + 1] = qx1;
            smA[qq][ap * 4 + 2] = qy0;
            smA[qq][ap * 4 + 3] = qy1;
            smB[qq][ap * 4 + 0] = qz0;
            smB[qq][ap * 4 + 1] = qz1;
            smB[qq][ap * 4 + 2] = s0;
            smB[qq][ap * 4 + 3] = s1;
            __syncthreads();

            const ulonglong2* vA = (const ulonglong2*)smA[qq];
            const ulonglong2* vB = (const ulonglong2*)smB[qq];
#pragma unroll 8
            for (int p = 0; p < 128; p++) {
                const ulonglong2 a = vA[p];   // (qx0,qx1)(qy0,qy1)
                const ulonglong2 c = vB[p];   // (qz0,qz1)(s0,s1)
                unsigned long long t0r = fma2(nx0, a.x, c.y);
                t0r = fma2(ny0, a.y, t0r);
                t0r = fma2(nz0, c.x, t0r);
                unsigned long long t1r = fma2(nx1, a.x, c.y);
                t1r = fma2(ny1, a.y, t1r);
                t1r = fma2(nz1, c.x, t1r);
                bl0 = fminf(bl0, lo2(t0r));
                bh0 = fminf(bh0, hi2(t0r));
                bl1 = fminf(bl1, lo2(t1r));
                bh1 = fminf(bh1, hi2(t1r));
            }
        }

        smC[tid][0] = fminf(bl0, bh0);
        smC[tid][1] = fminf(bl1, bh1);
        __syncthreads();

        float v = 0.f;
        if (tid < 128) {
            const float m0 = fminf(fminf(smC[tid][0], smC[tid + 128][0]),
                                   fminf(smC[tid + 256][0], smC[tid + 384][0]));
            const float m1 = fminf(fminf(smC[tid][1], smC[tid + 128][1]),
                                   fminf(smC[tid + 256][1], smC[tid + 384][1]));
            v = fmaf(2.f, m0, p2_0) + fmaf(2.f, m1, p2_1);
        }
        v = warp_sum(v);
        if (lane == 0) sred[wid] = v;
        __syncthreads();
        if (tid == 0) {
            float s = 0.f;
#pragma unroll
            for (int w = 0; w < 16; w++) s += sred[w];
            g_cham[cr] = s;
        }
    } else if (bid < CL_BLKS) {
        // ---------------- clDice (32 blocks) ----------------
        // erode(sigmoid(x)) == sigmoid(erode(x)); float4 along W; rolling d.
        const int task = bid * 512 + tid;          // 0..16383
        const int b = task >> 13;
        const int tloc = task & 8191;
        const int dchunk = tloc >> 12;             // 0..1
        const int cg = tloc & 4095;                // 128h * 32wg
        const int h = cg >> 5;
        const int w0 = (cg & 31) * 4;

        const float* P = pv + (size_t)b * VOX;
        const float* G = gv + (size_t)b * VOX;

        const int rm = (h > 0) ? h - 1 : 0;
        const int rp = (h < VOXH - 1) ? h + 1 : h;
        int rowoff[3];
        rowoff[0] = rm * VOXW + w0;
        rowoff[1] = h * VOXW + w0;
        rowoff[2] = rp * VOXW + w0;
        const bool hasL = (w0 > 0);
        const bool hasR = (w0 < VOXW - 4);

        auto inplane = [&](const float* __restrict__ V, int d) -> float4 {
            const int base = d << 14;
            float4 m = make_float4(FLT_MAX, FLT_MAX, FLT_MAX, FLT_MAX);
#pragma unroll
            for (int r = 0; r < 3; r++) {
                const float4 c4 = *(const float4*)(V + base + rowoff[r]);
                const float L = hasL ? __ldg(V + base + rowoff[r] - 1) : c4.x;
                const float R = hasR ? __ldg(V + base + rowoff[r] + 4) : c4.w;
                m.x = fminf(m.x, min3f(L, c4.x, c4.y));
                m.y = fminf(m.y, min3f(c4.x, c4.y, c4.z));
                m.z = fminf(m.z, min3f(c4.y, c4.z, c4.w));
                m.w = fminf(m.w, min3f(c4.z, c4.w, R));
            }
            return m;
        };

        const int d0 = dchunk * 32;
        float4 pPrev = inplane(P, (d0 > 0) ? d0 - 1 : 0);
        float4 gPrev = inplane(G, (d0 > 0) ? d0 - 1 : 0);
        float4 pCur = inplane(P, d0);
        float4 gCur = inplane(G, d0);

        float si = 0.f, sp = 0.f, sg = 0.f;
#pragma unroll 2
        for (int d = d0; d < d0 + 32; d++) {
            float4 pNext, gNext;
            if (d < VOXD - 1) {
                pNext = inplane(P, d + 1);
                gNext = inplane(G, d + 1);
            } else {
                pNext = pCur;
                gNext = gCur;
            }
            const float pox = min3f(pPrev.x, pCur.x, pNext.x);
            const float poy = min3f(pPrev.y, pCur.y, pNext.y);
            const float poz = min3f(pPrev.z, pCur.z, pNext.z);
            const float pow_ = min3f(pPrev.w, pCur.w, pNext.w);
            const float gox = min3f(gPrev.x, gCur.x, gNext.x);
            const float goy = min3f(gPrev.y, gCur.y, gNext.y);
            const float goz = min3f(gPrev.z, gCur.z, gNext.z);
            const float gow = min3f(gPrev.w, gCur.w, gNext.w);

            const float sx = __fdividef(1.f, 1.f + __expf(-pox));
            const float sy = __fdividef(1.f, 1.f + __expf(-poy));
            const float sz = __fdividef(1.f, 1.f + __expf(-poz));
            const float sw = __fdividef(1.f, 1.f + __expf(-pow_));

            si = fmaf(sx, gox, fmaf(sy, goy, fmaf(sz, goz, fmaf(sw, gow, si))));
            sp += (sx + sy) + (sz + sw);
            sg += (gox + goy) + (goz + gow);

            pPrev = pCur; gPrev = gCur;
            pCur = pNext; gCur = gNext;
        }

        // block spans a single batch (16 blocks per batch)
        float v0 = warp_sum(si), v1 = warp_sum(sp), v2 = warp_sum(sg);
        __shared__ float sr3[3][16];
        if (lane == 0) { sr3[0][wid] = v0; sr3[1][wid] = v1; sr3[2][wid] = v2; }
        __syncthreads();
        if (tid < 3) {
            float a = 0.f;
#pragma unroll
            for (int q = 0; q < 16; q++) a += sr3[tid][q];
            const int bb = bid >> 4;
            const int blk = bid & 15;
            g_cl[(bb * 16 + blk) * 3 + tid] = a;
        }
    } else {
        // ---------------- depth (16 blocks) ----------------
        const int rel = bid - CL_BLKS;
        const int b = rel >> 3;
        const int blk = rel & 7;
        const float* P = pd + (size_t)b * DPIX;
        const float* G = gd + (size_t)b * DPIX;
        const float* M = dm + (size_t)b * DPIX;

        float s0 = 0.f, s1 = 0.f, s2 = 0.f, s3 = 0.f, s4 = 0.f, s5 = 0.f;
        const int base = blk * (DPIX / 8);
#pragma unroll 4
        for (int k = 0; k < DPIX / 8 / 512; k++) {
            const int idx = base + k * 512 + tid;
            const int hh = idx >> 9;
            const int ww = idx & 511;
            const float p = P[idx];
            const float g = G[idx];
            const float lg = __logf(p + 0.1f) - __logf(g + 0.1f);
            s0 += lg;
            s1 = fmaf(lg, lg, s1);
            if (hh < 511) s2 += fabsf(fabsf(p - P[idx + 512]) - fabsf(g - G[idx + 512]));
            if (ww < 511) s3 += fabsf(fabsf(p - P[idx + 1]) - fabsf(g - G[idx + 1]));
            const float m = M[idx];
            s4 = fmaf(fabsf(p - g), m, s4);
            s5 += m;
        }

        __shared__ float sr6[6][16];
        float vs[6] = {s0, s1, s2, s3, s4, s5};
#pragma unroll
        for (int q = 0; q < 6; q++) {
            const float v = warp_sum(vs[q]);
            if (lane == 0) sr6[q][wid] = v;
        }
        __syncthreads();
        if (tid < 6) {
            float a = 0.f;
#pragma unroll
            for (int q = 0; q < 16; q++) a += sr6[tid][q];
            g_dp[(b * 8 + blk) * 6 + tid] = a;
        }
    }

    // ================= last-block finalize =================
    __threadfence();
    if (tid == 0) sflag = atomicAdd(&g_cnt, 1u);
    __syncthreads();
    if (sflag != TOT_BLKS - 1) return;
    if (tid == 0) g_cnt = 0;   // reset for next graph replay
    __threadfence();

    __shared__ float sq[7];
    __shared__ float sqd[6][2];

    if (wid == 0) {
        // chamfer total
        float v = 0.f;
#pragma unroll
        for (int i = lane; i < CHAM_BLKS; i += 32) v += g_cham[i];
        v = warp_sum(v);
        if (lane == 0) sq[0] = v;
    } else if (wid < 7) {
        const int idx = wid - 1;
        const int b = idx / 3, c = idx % 3;
        float v = (lane < 16) ? g_cl[(b * 16 + lane) * 3 + c] : 0.f;
        v = warp_sum(v);
        if (lane == 0) sq[wid] = v;
    } else if (wid < 13) {
        const int c = wid - 7;
        float v = 0.f;
        if (lane < 8) v = g_dp[lane * 6 + c];                 // b=0
        else if (lane < 16) v = g_dp[(8 + (lane - 8)) * 6 + c];  // b=1
        v += __shfl_down_sync(0xffffffffu, v, 4);
        v += __shfl_down_sync(0xffffffffu, v, 2);
        v += __shfl_down_sync(0xffffffffu, v, 1);
        if (lane == 0) sqd[c][0] = v;
        if (lane == 8) sqd[c][1] = v;
    }
    __syncthreads();

    if (tid == 0) {
        const float chamfer = sq[0] / (float)(BATCH * NPTS);

        float dice_acc = 0.f;
#pragma unroll
        for (int b = 0; b < BATCH; b++) {
            const float inter = sq[1 + b * 3 + 0];
            const float psum = sq[1 + b * 3 + 1];
            const float gsum = sq[1 + b * 3 + 2];
            dice_acc += (2.f * inter + 1e-5f) / (psum + gsum + 1e-5f);
        }
        const float cldice = 1.f - dice_acc / (float)BATCH;

        float var_acc = 0.f, m2_acc = 0.f;
#pragma unroll
        for (int b = 0; b < BATCH; b++) {
            const float mean = sqd[0][b] / (float)DPIX;
            const float var = sqd[1][b] / (float)DPIX - mean * mean;
            var_acc += var;
            m2_acc += mean * mean;
        }
        const float silog = 10.f * (var_acc / (float)BATCH) + 10.f * (m2_acc / (float)BATCH);

        const float gx = sqd[2][0] + sqd[2][1];
        const float gy = sqd[3][0] + sqd[3][1];
        const float grad_l1 = gx / (float)(BATCH * 511 * 512) + gy / (float)(BATCH * 512 * 511);

        const float mask_l1 = (sqd[4][0] + sqd[4][1]) / (sqd[5][0] + sqd[5][1] + 1e-8f);

        const float dloss = silog + grad_l1 + mask_l1;

        int it = iter[0];
        if (it < 1) it = 1;
        const float gamma1 = 2.f * logf((float)it / 20000.f);

        out[0] = gamma1 * chamfer + 0.5f * cldice + 0.01f * dloss;
    }
}

extern "C" void kernel_launch(void* const* d_in, const int* in_sizes, int n_in,
                              void* d_out, int out_size) {
    const float* pc = (const float*)d_in[0];   // pred_centers [2,8192,3]
    const float* pv = (const float*)d_in[1];   // pred_volume  [2,1,64,128,128]
    const float* pd = (const float*)d_in[2];   // pred_depth   [2,512,512]
    const float* gp = (const float*)d_in[3];   // gt_points    [2,8192,3]
    const float* gv = (const float*)d_in[4];   // gt_volume    [2,1,64,128,128]
    const float* gd = (const float*)d_in[5];   // gt_depth     [2,512,512]
    const float* dm = (const float*)d_in[6];   // depth_mask   [2,512,512]
    const int* it   = (const int*)d_in[7];     // iteration (scalar)

    mega_kernel<<<TOT_BLKS, 512>>>(pc, pv, pd, gp, gv, gd, dm, it, (float*)d_out);
}